// round 3
// baseline (speedup 1.0000x reference)
#include <cuda_runtime.h>
#include <math.h>

#define DIM   768
#define QKV3  2304
#define HID   3072
#define ROWS  8192      // 4 * 2048
#define SEQ   2048
#define NH    12
#define HD    64

// ---------------- scratch (static device allocs are the sanctioned path) ---
__device__ float g_ln [ROWS * DIM];
__device__ float g_qkv[ROWS * QKV3];
__device__ float g_att[ROWS * DIM];
__device__ float g_res[ROWS * DIM];
__device__ float g_h  [ROWS * HID];

// ---------------- LayerNorm: one block (256 thr) per row of 768 ------------
__global__ void __launch_bounds__(256) ln_kernel(
    const float* __restrict__ x, const float* __restrict__ w,
    const float* __restrict__ b, float* __restrict__ out)
{
    const int row = blockIdx.x;
    const float* xr = x + (size_t)row * DIM;
    float* orow = out + (size_t)row * DIM;
    const int t = threadIdx.x;

    float v0 = xr[t], v1 = xr[t + 256], v2 = xr[t + 512];
    float s  = v0 + v1 + v2;
    float ss = v0 * v0 + v1 * v1 + v2 * v2;

    __shared__ float red[16];
    #pragma unroll
    for (int o = 16; o > 0; o >>= 1) {
        s  += __shfl_xor_sync(0xffffffffu, s,  o);
        ss += __shfl_xor_sync(0xffffffffu, ss, o);
    }
    const int lane = t & 31, wid = t >> 5;
    if (lane == 0) { red[wid] = s; red[8 + wid] = ss; }
    __syncthreads();
    if (t == 0) {
        float a = 0.f, c = 0.f;
        #pragma unroll
        for (int i = 0; i < 8; i++) { a += red[i]; c += red[8 + i]; }
        float mean = a * (1.0f / DIM);
        float var  = c * (1.0f / DIM) - mean * mean;
        red[0] = mean;
        red[1] = rsqrtf(var + 1e-5f);
    }
    __syncthreads();
    const float mean = red[0], rstd = red[1];
    orow[t]       = (v0 - mean) * rstd * w[t]       + b[t];
    orow[t + 256] = (v1 - mean) * rstd * w[t + 256] + b[t + 256];
    orow[t + 512] = (v2 - mean) * rstd * w[t + 512] + b[t + 512];
}

// ---------------- GEMM-NT: C[M,N] = A[M,K] @ W[N,K]^T + bias (+R) (+GELU) --
// 128x128 tile, BK=8, 256 threads, 8x8 per thread.
template <int ACT, int RES>
__global__ void __launch_bounds__(256) gemm_nt(
    const float* __restrict__ A, const float* __restrict__ W,
    const float* __restrict__ bias, const float* __restrict__ R,
    float* __restrict__ C, int M, int N, int K)
{
    __shared__ float As[8][128];
    __shared__ float Ws[8][128];

    const int m0 = blockIdx.y * 128;
    const int n0 = blockIdx.x * 128;
    const int t  = threadIdx.x;
    const int tx = t & 15, ty = t >> 4;
    const int lrow = t >> 1;
    const int lk   = (t & 1) * 4;

    const float* Ap = A + (size_t)(m0 + lrow) * K + lk;
    const float* Wp = W + (size_t)(n0 + lrow) * K + lk;

    float acc[8][8];
    #pragma unroll
    for (int i = 0; i < 8; i++)
        #pragma unroll
        for (int j = 0; j < 8; j++) acc[i][j] = 0.f;

    for (int k0 = 0; k0 < K; k0 += 8) {
        float4 av = *(const float4*)(Ap + k0);
        float4 wv = *(const float4*)(Wp + k0);
        As[lk + 0][lrow] = av.x; As[lk + 1][lrow] = av.y;
        As[lk + 2][lrow] = av.z; As[lk + 3][lrow] = av.w;
        Ws[lk + 0][lrow] = wv.x; Ws[lk + 1][lrow] = wv.y;
        Ws[lk + 2][lrow] = wv.z; Ws[lk + 3][lrow] = wv.w;
        __syncthreads();
        #pragma unroll
        for (int kk = 0; kk < 8; kk++) {
            float a[8], bb[8];
            *(float4*)&a[0]  = *(const float4*)&As[kk][ty * 8];
            *(float4*)&a[4]  = *(const float4*)&As[kk][ty * 8 + 4];
            *(float4*)&bb[0] = *(const float4*)&Ws[kk][tx * 8];
            *(float4*)&bb[4] = *(const float4*)&Ws[kk][tx * 8 + 4];
            #pragma unroll
            for (int i = 0; i < 8; i++)
                #pragma unroll
                for (int j = 0; j < 8; j++)
                    acc[i][j] += a[i] * bb[j];
        }
        __syncthreads();
    }

    #pragma unroll
    for (int i = 0; i < 8; i++) {
        const int row = m0 + ty * 8 + i;
        const size_t base = (size_t)row * N + n0 + tx * 8;
        float tmp[8];
        #pragma unroll
        for (int j = 0; j < 8; j++) {
            const int col = n0 + tx * 8 + j;
            float c = acc[i][j] + bias[col];
            if (RES) c += R[(size_t)row * N + col];
            if (ACT) c = 0.5f * c * (1.0f + erff(c * 0.70710678118654752f));
            tmp[j] = c;
        }
        *(float4*)&C[base]     = make_float4(tmp[0], tmp[1], tmp[2], tmp[3]);
        *(float4*)&C[base + 4] = make_float4(tmp[4], tmp[5], tmp[6], tmp[7]);
    }
}

// ---------------- Flash attention: 128 q-rows per CTA, 64-key tiles --------
// qkv layout: [8192, 2304]; q at h*64, k at 768+h*64, v at 1536+h*64.
__global__ void __launch_bounds__(256) flash_kernel(
    const float* __restrict__ qkv, float* __restrict__ out)
{
    extern __shared__ float sm[];
    float (*Qs)[128] = (float(*)[128])(sm);            // [d][row]   8192
    float (*Ps)[128] = (float(*)[128])(sm + 8192);     // [key][row] 8192 (xor-swizzled rows)
    float (*Ks)[64]  = (float(*)[64]) (sm + 16384);    // [d][key]   4096
    float (*Vs)[64]  = (float(*)[64]) (sm + 20480);    // [key][d]   4096

    const int bh = blockIdx.y;
    const int b  = bh / NH, h = bh % NH;
    const int q0 = blockIdx.x * 128;
    const int t  = threadIdx.x, tx = t & 15, ty = t >> 4;

    // load Q tile (128 rows x 64 d) transposed into Qs[d][row]
    {
        const int row = t >> 1, d0 = (t & 1) * 32;
        const float* qp = qkv + (size_t)(b * SEQ + q0 + row) * QKV3 + h * HD + d0;
        #pragma unroll
        for (int u = 0; u < 8; u++) {
            float4 v4 = *(const float4*)(qp + u * 4);
            Qs[d0 + u * 4 + 0][row] = v4.x;
            Qs[d0 + u * 4 + 1][row] = v4.y;
            Qs[d0 + u * 4 + 2][row] = v4.z;
            Qs[d0 + u * 4 + 3][row] = v4.w;
        }
    }

    float mrun[8], lrun[8], acc[8][4];
    #pragma unroll
    for (int i = 0; i < 8; i++) {
        mrun[i] = -1e30f; lrun[i] = 0.f;
        #pragma unroll
        for (int j = 0; j < 4; j++) acc[i][j] = 0.f;
    }

    for (int k0 = 0; k0 < SEQ; k0 += 64) {
        // load K (transposed -> Ks[d][key]) and V (row-major -> Vs[key][d])
        {
            const int key = t >> 2, d0 = (t & 3) * 16;
            const float* kp = qkv + (size_t)(b * SEQ + k0 + key) * QKV3 +     DIM + h * HD + d0;
            const float* vp = qkv + (size_t)(b * SEQ + k0 + key) * QKV3 + 2 * DIM + h * HD + d0;
            #pragma unroll
            for (int u = 0; u < 4; u++) {
                float4 kv4 = *(const float4*)(kp + u * 4);
                Ks[d0 + u * 4 + 0][key] = kv4.x;
                Ks[d0 + u * 4 + 1][key] = kv4.y;
                Ks[d0 + u * 4 + 2][key] = kv4.z;
                Ks[d0 + u * 4 + 3][key] = kv4.w;
                *(float4*)&Vs[key][d0 + u * 4] = *(const float4*)(vp + u * 4);
            }
        }
        __syncthreads();

        // S = (Q K^T) * scale ; rows ty*8.., keys tx*4..
        float s[8][4];
        #pragma unroll
        for (int i = 0; i < 8; i++)
            #pragma unroll
            for (int j = 0; j < 4; j++) s[i][j] = 0.f;
        #pragma unroll 8
        for (int kk = 0; kk < 64; kk++) {
            float a[8], bb[4];
            *(float4*)&a[0]  = *(const float4*)&Qs[kk][ty * 8];
            *(float4*)&a[4]  = *(const float4*)&Qs[kk][ty * 8 + 4];
            *(float4*)&bb[0] = *(const float4*)&Ks[kk][tx * 4];
            #pragma unroll
            for (int i = 0; i < 8; i++)
                #pragma unroll
                for (int j = 0; j < 4; j++)
                    s[i][j] += a[i] * bb[j];
        }

        // online softmax over this key tile
        #pragma unroll
        for (int i = 0; i < 8; i++) {
            float tm = -1e30f;
            #pragma unroll
            for (int j = 0; j < 4; j++) { s[i][j] *= 0.125f; tm = fmaxf(tm, s[i][j]); }
            #pragma unroll
            for (int o = 8; o > 0; o >>= 1)
                tm = fmaxf(tm, __shfl_xor_sync(0xffffffffu, tm, o, 16));
            const float mnew = fmaxf(mrun[i], tm);
            const float corr = __expf(mrun[i] - mnew);
            float rs = 0.f;
            #pragma unroll
            for (int j = 0; j < 4; j++) {
                float p = __expf(s[i][j] - mnew);
                s[i][j] = p; rs += p;
            }
            #pragma unroll
            for (int o = 8; o > 0; o >>= 1)
                rs += __shfl_xor_sync(0xffffffffu, rs, o, 16);
            lrun[i] = lrun[i] * corr + rs;
            mrun[i] = mnew;
            #pragma unroll
            for (int j = 0; j < 4; j++) acc[i][j] *= corr;
            // store P with xor-swizzled row index (kills 16-way STS conflict)
            const int swb = (tx & 7) << 2;
            #pragma unroll
            for (int j = 0; j < 4; j++)
                Ps[tx * 4 + j][(ty * 8 + i) ^ swb] = s[i][j];
        }
        __syncthreads();

        // acc[row][d] += sum_key Ps[key][row] * Vs[key][d]
        #pragma unroll 8
        for (int kk = 0; kk < 64; kk++) {
            const int sw = ((kk >> 2) & 7) << 2;
            float a[8], bb[4];
            *(float4*)&a[0]  = *(const float4*)&Ps[kk][(ty * 8)     ^ sw];
            *(float4*)&a[4]  = *(const float4*)&Ps[kk][(ty * 8 + 4) ^ sw];
            *(float4*)&bb[0] = *(const float4*)&Vs[kk][tx * 4];
            #pragma unroll
            for (int i = 0; i < 8; i++)
                #pragma unroll
                for (int j = 0; j < 4; j++)
                    acc[i][j] += a[i] * bb[j];
        }
        __syncthreads();
    }

    // write normalized output: out[b*SEQ+row][h*64 + d]
    #pragma unroll
    for (int i = 0; i < 8; i++) {
        const float inv = 1.0f / lrun[i];
        const int row = q0 + ty * 8 + i;
        float* op = out + (size_t)(b * SEQ + row) * DIM + h * HD + tx * 4;
        float4 o = make_float4(acc[i][0] * inv, acc[i][1] * inv,
                               acc[i][2] * inv, acc[i][3] * inv);
        *(float4*)op = o;
    }
}

// ---------------------------------------------------------------------------
extern "C" void kernel_launch(void* const* d_in, const int* in_sizes, int n_in,
                              void* d_out, int out_size)
{
    const float* x      = (const float*)d_in[0];
    const float* ln1_w  = (const float*)d_in[1];
    const float* ln1_b  = (const float*)d_in[2];
    const float* qkv_w  = (const float*)d_in[3];
    const float* qkv_b  = (const float*)d_in[4];
    const float* proj_w = (const float*)d_in[5];
    const float* proj_b = (const float*)d_in[6];
    const float* ln2_w  = (const float*)d_in[7];
    const float* ln2_b  = (const float*)d_in[8];
    const float* fc1_w  = (const float*)d_in[9];
    const float* fc1_b  = (const float*)d_in[10];
    const float* fc2_w  = (const float*)d_in[11];
    const float* fc2_b  = (const float*)d_in[12];
    float* out = (float*)d_out;

    float *p_ln, *p_qkv, *p_att, *p_res, *p_h;
    cudaGetSymbolAddress((void**)&p_ln,  g_ln);
    cudaGetSymbolAddress((void**)&p_qkv, g_qkv);
    cudaGetSymbolAddress((void**)&p_att, g_att);
    cudaGetSymbolAddress((void**)&p_res, g_res);
    cudaGetSymbolAddress((void**)&p_h,   g_h);

    cudaFuncSetAttribute(flash_kernel,
                         cudaFuncAttributeMaxDynamicSharedMemorySize, 98304);

    // 1) ln1(x) -> g_ln
    ln_kernel<<<ROWS, 256>>>(x, ln1_w, ln1_b, p_ln);
    // 2) qkv = ln1 @ qkv_w^T + qkv_b -> g_qkv
    gemm_nt<0, 0><<<dim3(QKV3 / 128, ROWS / 128), 256>>>(
        p_ln, qkv_w, qkv_b, nullptr, p_qkv, ROWS, QKV3, DIM);
    // 3) attention -> g_att
    flash_kernel<<<dim3(SEQ / 128, 4 * NH), 256, 98304>>>(p_qkv, p_att);
    // 4) x1 = att @ proj_w^T + proj_b + x -> g_res
    gemm_nt<0, 1><<<dim3(DIM / 128, ROWS / 128), 256>>>(
        p_att, proj_w, proj_b, x, p_res, ROWS, DIM, DIM);
    // 5) ln2(x1) -> g_ln
    ln_kernel<<<ROWS, 256>>>(p_res, ln2_w, ln2_b, p_ln);
    // 6) h = gelu(ln2 @ fc1_w^T + fc1_b) -> g_h
    gemm_nt<1, 0><<<dim3(HID / 128, ROWS / 128), 256>>>(
        p_ln, fc1_w, fc1_b, nullptr, p_h, ROWS, HID, DIM);
    // 7) out = h @ fc2_w^T + fc2_b + x1
    gemm_nt<0, 1><<<dim3(DIM / 128, ROWS / 128), 256>>>(
        p_h, fc2_w, fc2_b, p_res, out, ROWS, DIM, HID);
}

// round 5
// speedup vs baseline: 1.8362x; 1.8362x over previous
#include <cuda_runtime.h>
#include <cuda_bf16.h>
#include <math.h>
#include <stdint.h>

#define DIM   768
#define QKV3  2304
#define HID   3072
#define ROWS  8192      // 4 * 2048
#define SEQ   2048
#define NH    12
#define HD    64

// ---------------- scratch ---------------------------------------------------
__device__ float g_ln [ROWS * DIM];
__device__ float g_qkv[ROWS * QKV3];
__device__ float g_att[ROWS * DIM];
__device__ float g_res[ROWS * DIM];
__device__ float g_h  [ROWS * HID];

// ---------------- helpers ---------------------------------------------------
__device__ __forceinline__ uint32_t smem_u32(const void* p) {
    uint32_t a;
    asm("{ .reg .u64 t; cvta.to.shared.u64 t, %1; cvt.u32.u64 %0, t; }"
        : "=r"(a) : "l"(p));
    return a;
}

__device__ __forceinline__ void ldsm4(uint32_t* r, uint32_t addr) {
    asm volatile("ldmatrix.sync.aligned.m8n8.x4.shared.b16 {%0,%1,%2,%3}, [%4];"
                 : "=r"(r[0]), "=r"(r[1]), "=r"(r[2]), "=r"(r[3]) : "r"(addr));
}

__device__ __forceinline__ void mma16816(float* c, const uint32_t* a,
                                         const uint32_t* b) {
    asm volatile(
        "mma.sync.aligned.m16n8k16.row.col.f32.bf16.bf16.f32 "
        "{%0,%1,%2,%3}, {%4,%5,%6,%7}, {%8,%9}, {%0,%1,%2,%3};"
        : "+f"(c[0]), "+f"(c[1]), "+f"(c[2]), "+f"(c[3])
        : "r"(a[0]), "r"(a[1]), "r"(a[2]), "r"(a[3]), "r"(b[0]), "r"(b[1]));
}

// ---------------- LayerNorm -------------------------------------------------
__global__ void __launch_bounds__(256) ln_kernel(
    const float* __restrict__ x, const float* __restrict__ w,
    const float* __restrict__ b, float* __restrict__ out)
{
    const int row = blockIdx.x;
    const float* xr = x + (size_t)row * DIM;
    float* orow = out + (size_t)row * DIM;
    const int t = threadIdx.x;

    float v0 = xr[t], v1 = xr[t + 256], v2 = xr[t + 512];
    float s  = v0 + v1 + v2;
    float ss = v0 * v0 + v1 * v1 + v2 * v2;

    __shared__ float red[16];
    #pragma unroll
    for (int o = 16; o > 0; o >>= 1) {
        s  += __shfl_xor_sync(0xffffffffu, s,  o);
        ss += __shfl_xor_sync(0xffffffffu, ss, o);
    }
    const int lane = t & 31, wid = t >> 5;
    if (lane == 0) { red[wid] = s; red[8 + wid] = ss; }
    __syncthreads();
    if (t == 0) {
        float a = 0.f, c = 0.f;
        #pragma unroll
        for (int i = 0; i < 8; i++) { a += red[i]; c += red[8 + i]; }
        float mean = a * (1.0f / DIM);
        float var  = c * (1.0f / DIM) - mean * mean;
        red[0] = mean;
        red[1] = rsqrtf(var + 1e-5f);
    }
    __syncthreads();
    const float mean = red[0], rstd = red[1];
    orow[t]       = (v0 - mean) * rstd * w[t]       + b[t];
    orow[t + 256] = (v1 - mean) * rstd * w[t + 256] + b[t + 256];
    orow[t + 512] = (v2 - mean) * rstd * w[t + 512] + b[t + 512];
}

// ---------------- HMMA bf16x3-split GEMM-NT ---------------------------------
// C[M,N] = A[M,K] @ W[N,K]^T + bias (+R) (+GELU), fp32 in/out.
// CTA 128x128, BK=32, 8 warps (4m x 2n), warp tile 32x64 (2x8 m16n8 tiles).
// smem tile: 128 rows x 32 bf16, row stride 80B (conflict-free STS + ldmatrix).
#define MT_ROWPITCH 80u
#define MT_TILE     (128u * MT_ROWPITCH)   // 10240
#define MT_STAGE    (4u * MT_TILE)         // Ah Al Bh Bl = 40960
#define MT_SMEM     (2u * MT_STAGE)        // 81920

// split fp32 -> bf16 hi (truncate) + bf16 lo (round of exact remainder)
__device__ __forceinline__ void split4(const float4 v, uint2& h, uint2& l) {
    uint32_t a0 = __float_as_uint(v.x), a1 = __float_as_uint(v.y);
    uint32_t a2 = __float_as_uint(v.z), a3 = __float_as_uint(v.w);
    h.x = (a0 >> 16) | (a1 & 0xFFFF0000u);
    h.y = (a2 >> 16) | (a3 & 0xFFFF0000u);
    float l0 = v.x - __uint_as_float(a0 & 0xFFFF0000u);
    float l1 = v.y - __uint_as_float(a1 & 0xFFFF0000u);
    float l2 = v.z - __uint_as_float(a2 & 0xFFFF0000u);
    float l3 = v.w - __uint_as_float(a3 & 0xFFFF0000u);
    asm("cvt.rn.bf16x2.f32 %0, %1, %2;" : "=r"(l.x) : "f"(l1), "f"(l0));
    asm("cvt.rn.bf16x2.f32 %0, %1, %2;" : "=r"(l.y) : "f"(l3), "f"(l2));
}

template <int ACT, int RES>
__global__ void __launch_bounds__(256, 1) gemm_mma(
    const float* __restrict__ A, const float* __restrict__ W,
    const float* __restrict__ bias, const float* __restrict__ R,
    float* __restrict__ C, int M, int N, int K)
{
    extern __shared__ __align__(16) char sm[];
    const uint32_t sb = smem_u32(sm);

    const int t    = threadIdx.x;
    const int lane = t & 31, wid = t >> 5;
    const int mw   = wid & 3, nw = wid >> 2;
    const int m0   = blockIdx.y * 128, n0 = blockIdx.x * 128;
    const int NC   = K >> 5;

    const float* Ap = A + (size_t)m0 * K;
    const float* Wp = W + (size_t)n0 * K;

    float cfr[2][8][4];
    #pragma unroll
    for (int i = 0; i < 2; i++)
        #pragma unroll
        for (int j = 0; j < 8; j++)
            #pragma unroll
            for (int k = 0; k < 4; k++) cfr[i][j][k] = 0.f;

    const int srow = t >> 3;          // 0..127  (loader mapping)
    const int sc4  = t & 7;           // 0..7 float4s per row
    float4 ra[4], rb[4];

    // ---- prologue: chunk 0 ----
    #pragma unroll
    for (int u = 0; u < 4; u++) {
        int i = t + u * 256, r = i >> 3, c4 = i & 7;
        ra[u] = *(const float4*)(Ap + (size_t)r * K + c4 * 4);
        rb[u] = *(const float4*)(Wp + (size_t)r * K + c4 * 4);
    }
    {
        char* st = sm;
        #pragma unroll
        for (int u = 0; u < 4; u++) {
            int i = t + u * 256, r = i >> 3, c4 = i & 7;
            uint32_t off = (uint32_t)r * MT_ROWPITCH + c4 * 8;
            uint2 h, l;
            split4(ra[u], h, l);
            *(uint2*)(st + off)            = h;
            *(uint2*)(st + MT_TILE + off)  = l;
            split4(rb[u], h, l);
            *(uint2*)(st + 2 * MT_TILE + off) = h;
            *(uint2*)(st + 3 * MT_TILE + off) = l;
        }
    }
    __syncthreads();

    const uint32_t a_lane = (uint32_t)(mw * 32 + (lane & 15)) * MT_ROWPITCH
                          + ((lane >> 4) * 16);
    const uint32_t b_lane = (uint32_t)(nw * 64 + (lane & 7)
                          + (((lane >> 4) & 1) * 8)) * MT_ROWPITCH
                          + (((lane >> 3) & 1) * 16);

    for (int c = 0; c < NC; c++) {
        // prefetch next chunk into regs (overlaps with MMA below)
        if (c + 1 < NC) {
            const int kc = (c + 1) << 5;
            #pragma unroll
            for (int u = 0; u < 4; u++) {
                int i = t + u * 256, r = i >> 3, c4 = i & 7;
                ra[u] = *(const float4*)(Ap + (size_t)r * K + kc + c4 * 4);
                rb[u] = *(const float4*)(Wp + (size_t)r * K + kc + c4 * 4);
            }
        }

        const uint32_t stage = sb + (uint32_t)(c & 1) * MT_STAGE;
        #pragma unroll
        for (int ks = 0; ks < 2; ks++) {
            uint32_t ah[2][4], al[2][4];
            #pragma unroll
            for (int mt = 0; mt < 2; mt++) {
                uint32_t aoff = a_lane + (uint32_t)mt * (16 * MT_ROWPITCH)
                              + ks * 32;
                ldsm4(ah[mt], stage + aoff);
                ldsm4(al[mt], stage + MT_TILE + aoff);
            }
            #pragma unroll
            for (int p = 0; p < 4; p++) {
                uint32_t bh[4], bl[4];
                uint32_t boff = b_lane + (uint32_t)p * (16 * MT_ROWPITCH)
                              + ks * 32;
                ldsm4(bh, stage + 2 * MT_TILE + boff);
                ldsm4(bl, stage + 3 * MT_TILE + boff);
                #pragma unroll
                for (int mt = 0; mt < 2; mt++) {
                    #pragma unroll
                    for (int q = 0; q < 2; q++) {
                        float* cc = cfr[mt][2 * p + q];
                        mma16816(cc, ah[mt], &bh[q * 2]);
                        mma16816(cc, ah[mt], &bl[q * 2]);
                        mma16816(cc, al[mt], &bh[q * 2]);
                    }
                }
            }
        }

        // store next chunk into the other stage
        if (c + 1 < NC) {
            char* st = sm + ((c + 1) & 1) * MT_STAGE;
            #pragma unroll
            for (int u = 0; u < 4; u++) {
                int i = t + u * 256, r = i >> 3, c4 = i & 7;
                uint32_t off = (uint32_t)r * MT_ROWPITCH + c4 * 8;
                uint2 h, l;
                split4(ra[u], h, l);
                *(uint2*)(st + off)            = h;
                *(uint2*)(st + MT_TILE + off)  = l;
                split4(rb[u], h, l);
                *(uint2*)(st + 2 * MT_TILE + off) = h;
                *(uint2*)(st + 3 * MT_TILE + off) = l;
            }
        }
        __syncthreads();
    }

    // ---- epilogue: fragments -> global with bias/res/gelu ----
    const int er0 = m0 + mw * 32 + (lane >> 2);
    const int ec0 = n0 + nw * 64 + (lane & 3) * 2;
    #pragma unroll
    for (int mt = 0; mt < 2; mt++) {
        #pragma unroll
        for (int nt = 0; nt < 8; nt++) {
            const int col = ec0 + nt * 8;
            const float2 bv = *(const float2*)(bias + col);
            #pragma unroll
            for (int half = 0; half < 2; half++) {
                const int row = er0 + mt * 16 + half * 8;
                float vx = cfr[mt][nt][half * 2 + 0] + bv.x;
                float vy = cfr[mt][nt][half * 2 + 1] + bv.y;
                if (RES) {
                    const float2 rv = *(const float2*)(R + (size_t)row * N + col);
                    vx += rv.x; vy += rv.y;
                }
                if (ACT) {
                    vx = 0.5f * vx * (1.0f + erff(vx * 0.70710678118654752f));
                    vy = 0.5f * vy * (1.0f + erff(vy * 0.70710678118654752f));
                }
                *(float2*)(C + (size_t)row * N + col) = make_float2(vx, vy);
            }
        }
    }
}

// ---------------- Flash attention (fp32) ------------------------------------
__global__ void __launch_bounds__(256) flash_kernel(
    const float* __restrict__ qkv, float* __restrict__ out)
{
    extern __shared__ float smf[];
    float (*Qs)[128] = (float(*)[128])(smf);
    float (*Ps)[128] = (float(*)[128])(smf + 8192);
    float (*Ks)[64]  = (float(*)[64]) (smf + 16384);
    float (*Vs)[64]  = (float(*)[64]) (smf + 20480);

    const int bh = blockIdx.y;
    const int b  = bh / NH, h = bh % NH;
    const int q0 = blockIdx.x * 128;
    const int t  = threadIdx.x, tx = t & 15, ty = t >> 4;

    {
        const int row = t >> 1, d0 = (t & 1) * 32;
        const float* qp = qkv + (size_t)(b * SEQ + q0 + row) * QKV3 + h * HD + d0;
        #pragma unroll
        for (int u = 0; u < 8; u++) {
            float4 v4 = *(const float4*)(qp + u * 4);
            Qs[d0 + u * 4 + 0][row] = v4.x;
            Qs[d0 + u * 4 + 1][row] = v4.y;
            Qs[d0 + u * 4 + 2][row] = v4.z;
            Qs[d0 + u * 4 + 3][row] = v4.w;
        }
    }

    float mrun[8], lrun[8], acc[8][4];
    #pragma unroll
    for (int i = 0; i < 8; i++) {
        mrun[i] = -1e30f; lrun[i] = 0.f;
        #pragma unroll
        for (int j = 0; j < 4; j++) acc[i][j] = 0.f;
    }

    for (int k0 = 0; k0 < SEQ; k0 += 64) {
        {
            const int key = t >> 2, d0 = (t & 3) * 16;
            const float* kp = qkv + (size_t)(b * SEQ + k0 + key) * QKV3 +     DIM + h * HD + d0;
            const float* vp = qkv + (size_t)(b * SEQ + k0 + key) * QKV3 + 2 * DIM + h * HD + d0;
            #pragma unroll
            for (int u = 0; u < 4; u++) {
                float4 kv4 = *(const float4*)(kp + u * 4);
                Ks[d0 + u * 4 + 0][key] = kv4.x;
                Ks[d0 + u * 4 + 1][key] = kv4.y;
                Ks[d0 + u * 4 + 2][key] = kv4.z;
                Ks[d0 + u * 4 + 3][key] = kv4.w;
                *(float4*)&Vs[key][d0 + u * 4] = *(const float4*)(vp + u * 4);
            }
        }
        __syncthreads();

        float s[8][4];
        #pragma unroll
        for (int i = 0; i < 8; i++)
            #pragma unroll
            for (int j = 0; j < 4; j++) s[i][j] = 0.f;
        #pragma unroll 8
        for (int kk = 0; kk < 64; kk++) {
            float a[8], bb[4];
            *(float4*)&a[0]  = *(const float4*)&Qs[kk][ty * 8];
            *(float4*)&a[4]  = *(const float4*)&Qs[kk][ty * 8 + 4];
            *(float4*)&bb[0] = *(const float4*)&Ks[kk][tx * 4];
            #pragma unroll
            for (int i = 0; i < 8; i++)
                #pragma unroll
                for (int j = 0; j < 4; j++)
                    s[i][j] += a[i] * bb[j];
        }

        #pragma unroll
        for (int i = 0; i < 8; i++) {
            float tm = -1e30f;
            #pragma unroll
            for (int j = 0; j < 4; j++) { s[i][j] *= 0.125f; tm = fmaxf(tm, s[i][j]); }
            #pragma unroll
            for (int o = 8; o > 0; o >>= 1)
                tm = fmaxf(tm, __shfl_xor_sync(0xffffffffu, tm, o, 16));
            const float mnew = fmaxf(mrun[i], tm);
            const float corr = __expf(mrun[i] - mnew);
            float rs = 0.f;
            #pragma unroll
            for (int j = 0; j < 4; j++) {
                float p = __expf(s[i][j] - mnew);
                s[i][j] = p; rs += p;
            }
            #pragma unroll
            for (int o = 8; o > 0; o >>= 1)
                rs += __shfl_xor_sync(0xffffffffu, rs, o, 16);
            lrun[i] = lrun[i] * corr + rs;
            mrun[i] = mnew;
            #pragma unroll
            for (int j = 0; j < 4; j++) acc[i][j] *= corr;
            const int swb = (tx & 7) << 2;
            #pragma unroll
            for (int j = 0; j < 4; j++)
                Ps[tx * 4 + j][(ty * 8 + i) ^ swb] = s[i][j];
        }
        __syncthreads();

        #pragma unroll 8
        for (int kk = 0; kk < 64; kk++) {
            const int sw = ((kk >> 2) & 7) << 2;
            float a[8], bb[4];
            *(float4*)&a[0]  = *(const float4*)&Ps[kk][(ty * 8)     ^ sw];
            *(float4*)&a[4]  = *(const float4*)&Ps[kk][(ty * 8 + 4) ^ sw];
            *(float4*)&bb[0] = *(const float4*)&Vs[kk][tx * 4];
            #pragma unroll
            for (int i = 0; i < 8; i++)
                #pragma unroll
                for (int j = 0; j < 4; j++)
                    acc[i][j] += a[i] * bb[j];
        }
        __syncthreads();
    }

    #pragma unroll
    for (int i = 0; i < 8; i++) {
        const float inv = 1.0f / lrun[i];
        const int row = q0 + ty * 8 + i;
        float* op = out + (size_t)(b * SEQ + row) * DIM + h * HD + tx * 4;
        float4 o = make_float4(acc[i][0] * inv, acc[i][1] * inv,
                               acc[i][2] * inv, acc[i][3] * inv);
        *(float4*)op = o;
    }
}

// ---------------------------------------------------------------------------
extern "C" void kernel_launch(void* const* d_in, const int* in_sizes, int n_in,
                              void* d_out, int out_size)
{
    const float* x      = (const float*)d_in[0];
    const float* ln1_w  = (const float*)d_in[1];
    const float* ln1_b  = (const float*)d_in[2];
    const float* qkv_w  = (const float*)d_in[3];
    const float* qkv_b  = (const float*)d_in[4];
    const float* proj_w = (const float*)d_in[5];
    const float* proj_b = (const float*)d_in[6];
    const float* ln2_w  = (const float*)d_in[7];
    const float* ln2_b  = (const float*)d_in[8];
    const float* fc1_w  = (const float*)d_in[9];
    const float* fc1_b  = (const float*)d_in[10];
    const float* fc2_w  = (const float*)d_in[11];
    const float* fc2_b  = (const float*)d_in[12];
    float* out = (float*)d_out;

    float *p_ln, *p_qkv, *p_att, *p_res, *p_h;
    cudaGetSymbolAddress((void**)&p_ln,  g_ln);
    cudaGetSymbolAddress((void**)&p_qkv, g_qkv);
    cudaGetSymbolAddress((void**)&p_att, g_att);
    cudaGetSymbolAddress((void**)&p_res, g_res);
    cudaGetSymbolAddress((void**)&p_h,   g_h);

    cudaFuncSetAttribute(flash_kernel,
                         cudaFuncAttributeMaxDynamicSharedMemorySize, 98304);
    cudaFuncSetAttribute(gemm_mma<0, 0>,
                         cudaFuncAttributeMaxDynamicSharedMemorySize, MT_SMEM);
    cudaFuncSetAttribute(gemm_mma<0, 1>,
                         cudaFuncAttributeMaxDynamicSharedMemorySize, MT_SMEM);
    cudaFuncSetAttribute(gemm_mma<1, 0>,
                         cudaFuncAttributeMaxDynamicSharedMemorySize, MT_SMEM);

    // 1) ln1(x) -> g_ln
    ln_kernel<<<ROWS, 256>>>(x, ln1_w, ln1_b, p_ln);
    // 2) qkv = ln1 @ qkv_w^T + qkv_b -> g_qkv
    gemm_mma<0, 0><<<dim3(QKV3 / 128, ROWS / 128), 256, MT_SMEM>>>(
        p_ln, qkv_w, qkv_b, nullptr, p_qkv, ROWS, QKV3, DIM);
    // 3) attention -> g_att
    flash_kernel<<<dim3(SEQ / 128, 4 * NH), 256, 98304>>>(p_qkv, p_att);
    // 4) x1 = att @ proj_w^T + proj_b + x -> g_res
    gemm_mma<0, 1><<<dim3(DIM / 128, ROWS / 128), 256, MT_SMEM>>>(
        p_att, proj_w, proj_b, x, p_res, ROWS, DIM, DIM);
    // 5) ln2(x1) -> g_ln
    ln_kernel<<<ROWS, 256>>>(p_res, ln2_w, ln2_b, p_ln);
    // 6) h = gelu(ln2 @ fc1_w^T + fc1_b) -> g_h
    gemm_mma<1, 0><<<dim3(HID / 128, ROWS / 128), 256, MT_SMEM>>>(
        p_ln, fc1_w, fc1_b, nullptr, p_h, ROWS, HID, DIM);
    // 7) out = h @ fc2_w^T + fc2_b + x1
    gemm_mma<0, 1><<<dim3(DIM / 128, ROWS / 128), 256, MT_SMEM>>>(
        p_h, fc2_w, fc2_b, p_res, out, ROWS, DIM, HID);
}

// round 7
// speedup vs baseline: 2.7843x; 1.5163x over previous
#include <cuda_runtime.h>
#include <cuda_bf16.h>
#include <math.h>
#include <stdint.h>

#define DIM   768
#define QKV3  2304
#define HID   3072
#define ROWS  8192      // 4 * 2048
#define SEQ   2048
#define NH    12
#define HD    64

// ---------------- scratch ---------------------------------------------------
__device__ float g_ln [ROWS * DIM];
__device__ float g_qkv[ROWS * QKV3];
__device__ float g_att[ROWS * DIM];
__device__ float g_res[ROWS * DIM];
__device__ float g_h  [ROWS * HID];

// ---------------- helpers ---------------------------------------------------
__device__ __forceinline__ uint32_t smem_u32(const void* p) {
    uint32_t a;
    asm("{ .reg .u64 t; cvta.to.shared.u64 t, %1; cvt.u32.u64 %0, t; }"
        : "=r"(a) : "l"(p));
    return a;
}

__device__ __forceinline__ void ldsm4(uint32_t* r, uint32_t addr) {
    asm volatile("ldmatrix.sync.aligned.m8n8.x4.shared.b16 {%0,%1,%2,%3}, [%4];"
                 : "=r"(r[0]), "=r"(r[1]), "=r"(r[2]), "=r"(r[3]) : "r"(addr));
}

__device__ __forceinline__ void mma16816(float* c, const uint32_t* a,
                                         const uint32_t* b) {
    asm volatile(
        "mma.sync.aligned.m16n8k16.row.col.f32.bf16.bf16.f32 "
        "{%0,%1,%2,%3}, {%4,%5,%6,%7}, {%8,%9}, {%0,%1,%2,%3};"
        : "+f"(c[0]), "+f"(c[1]), "+f"(c[2]), "+f"(c[3])
        : "r"(a[0]), "r"(a[1]), "r"(a[2]), "r"(a[3]), "r"(b[0]), "r"(b[1]));
}

// pack hi (truncated) bf16x2 of two fp32
__device__ __forceinline__ uint32_t hipack(float x, float y) {
    return (__float_as_uint(x) >> 16) | (__float_as_uint(y) & 0xFFFF0000u);
}
// pack lo residual bf16x2 of two fp32
__device__ __forceinline__ uint32_t lopack(float x, float y) {
    float rx = x - __uint_as_float(__float_as_uint(x) & 0xFFFF0000u);
    float ry = y - __uint_as_float(__float_as_uint(y) & 0xFFFF0000u);
    uint32_t r;
    asm("cvt.rn.bf16x2.f32 %0, %1, %2;" : "=r"(r) : "f"(ry), "f"(rx));
    return r;
}

// split fp32x4 -> bf16 hi (truncate) + bf16 lo (round of exact remainder)
__device__ __forceinline__ void split4(const float4 v, uint2& h, uint2& l) {
    h.x = hipack(v.x, v.y);
    h.y = hipack(v.z, v.w);
    l.x = lopack(v.x, v.y);
    l.y = lopack(v.z, v.w);
}

// ---------------- LayerNorm -------------------------------------------------
__global__ void __launch_bounds__(256) ln_kernel(
    const float* __restrict__ x, const float* __restrict__ w,
    const float* __restrict__ b, float* __restrict__ out)
{
    const int row = blockIdx.x;
    const float* xr = x + (size_t)row * DIM;
    float* orow = out + (size_t)row * DIM;
    const int t = threadIdx.x;

    float v0 = xr[t], v1 = xr[t + 256], v2 = xr[t + 512];
    float s  = v0 + v1 + v2;
    float ss = v0 * v0 + v1 * v1 + v2 * v2;

    __shared__ float red[16];
    #pragma unroll
    for (int o = 16; o > 0; o >>= 1) {
        s  += __shfl_xor_sync(0xffffffffu, s,  o);
        ss += __shfl_xor_sync(0xffffffffu, ss, o);
    }
    const int lane = t & 31, wid = t >> 5;
    if (lane == 0) { red[wid] = s; red[8 + wid] = ss; }
    __syncthreads();
    if (t == 0) {
        float a = 0.f, c = 0.f;
        #pragma unroll
        for (int i = 0; i < 8; i++) { a += red[i]; c += red[8 + i]; }
        float mean = a * (1.0f / DIM);
        float var  = c * (1.0f / DIM) - mean * mean;
        red[0] = mean;
        red[1] = rsqrtf(var + 1e-5f);
    }
    __syncthreads();
    const float mean = red[0], rstd = red[1];
    orow[t]       = (v0 - mean) * rstd * w[t]       + b[t];
    orow[t + 256] = (v1 - mean) * rstd * w[t + 256] + b[t + 256];
    orow[t + 512] = (v2 - mean) * rstd * w[t + 512] + b[t + 512];
}

// ---------------- HMMA bf16x3-split GEMM-NT ---------------------------------
#define MT_ROWPITCH 80u
#define MT_TILE     (128u * MT_ROWPITCH)   // 10240
#define MT_STAGE    (4u * MT_TILE)         // Ah Al Bh Bl = 40960
#define MT_SMEM     (2u * MT_STAGE)        // 81920

template <int ACT, int RES>
__global__ void __launch_bounds__(256, 1) gemm_mma(
    const float* __restrict__ A, const float* __restrict__ W,
    const float* __restrict__ bias, const float* __restrict__ R,
    float* __restrict__ C, int M, int N, int K)
{
    extern __shared__ __align__(16) char sm[];
    const uint32_t sb = smem_u32(sm);

    const int t    = threadIdx.x;
    const int lane = t & 31, wid = t >> 5;
    const int mw   = wid & 3, nw = wid >> 2;
    const int m0   = blockIdx.y * 128, n0 = blockIdx.x * 128;
    const int NC   = K >> 5;

    const float* Ap = A + (size_t)m0 * K;
    const float* Wp = W + (size_t)n0 * K;

    float cfr[2][8][4];
    #pragma unroll
    for (int i = 0; i < 2; i++)
        #pragma unroll
        for (int j = 0; j < 8; j++)
            #pragma unroll
            for (int k = 0; k < 4; k++) cfr[i][j][k] = 0.f;

    float4 ra[4], rb[4];
    #pragma unroll
    for (int u = 0; u < 4; u++) {
        int i = t + u * 256, r = i >> 3, c4 = i & 7;
        ra[u] = *(const float4*)(Ap + (size_t)r * K + c4 * 4);
        rb[u] = *(const float4*)(Wp + (size_t)r * K + c4 * 4);
    }
    {
        char* st = sm;
        #pragma unroll
        for (int u = 0; u < 4; u++) {
            int i = t + u * 256, r = i >> 3, c4 = i & 7;
            uint32_t off = (uint32_t)r * MT_ROWPITCH + c4 * 8;
            uint2 h, l;
            split4(ra[u], h, l);
            *(uint2*)(st + off)            = h;
            *(uint2*)(st + MT_TILE + off)  = l;
            split4(rb[u], h, l);
            *(uint2*)(st + 2 * MT_TILE + off) = h;
            *(uint2*)(st + 3 * MT_TILE + off) = l;
        }
    }
    __syncthreads();

    const uint32_t a_lane = (uint32_t)(mw * 32 + (lane & 15)) * MT_ROWPITCH
                          + ((lane >> 4) * 16);
    const uint32_t b_lane = (uint32_t)(nw * 64 + (lane & 7)
                          + (((lane >> 4) & 1) * 8)) * MT_ROWPITCH
                          + (((lane >> 3) & 1) * 16);

    for (int c = 0; c < NC; c++) {
        if (c + 1 < NC) {
            const int kc = (c + 1) << 5;
            #pragma unroll
            for (int u = 0; u < 4; u++) {
                int i = t + u * 256, r = i >> 3, c4 = i & 7;
                ra[u] = *(const float4*)(Ap + (size_t)r * K + kc + c4 * 4);
                rb[u] = *(const float4*)(Wp + (size_t)r * K + kc + c4 * 4);
            }
        }

        const uint32_t stage = sb + (uint32_t)(c & 1) * MT_STAGE;
        #pragma unroll
        for (int ks = 0; ks < 2; ks++) {
            uint32_t ah[2][4], al[2][4];
            #pragma unroll
            for (int mt = 0; mt < 2; mt++) {
                uint32_t aoff = a_lane + (uint32_t)mt * (16 * MT_ROWPITCH)
                              + ks * 32;
                ldsm4(ah[mt], stage + aoff);
                ldsm4(al[mt], stage + MT_TILE + aoff);
            }
            #pragma unroll
            for (int p = 0; p < 4; p++) {
                uint32_t bh[4], bl[4];
                uint32_t boff = b_lane + (uint32_t)p * (16 * MT_ROWPITCH)
                              + ks * 32;
                ldsm4(bh, stage + 2 * MT_TILE + boff);
                ldsm4(bl, stage + 3 * MT_TILE + boff);
                #pragma unroll
                for (int mt = 0; mt < 2; mt++) {
                    #pragma unroll
                    for (int q = 0; q < 2; q++) {
                        float* cc = cfr[mt][2 * p + q];
                        mma16816(cc, ah[mt], &bh[q * 2]);
                        mma16816(cc, ah[mt], &bl[q * 2]);
                        mma16816(cc, al[mt], &bh[q * 2]);
                    }
                }
            }
        }

        if (c + 1 < NC) {
            char* st = sm + ((c + 1) & 1) * MT_STAGE;
            #pragma unroll
            for (int u = 0; u < 4; u++) {
                int i = t + u * 256, r = i >> 3, c4 = i & 7;
                uint32_t off = (uint32_t)r * MT_ROWPITCH + c4 * 8;
                uint2 h, l;
                split4(ra[u], h, l);
                *(uint2*)(st + off)            = h;
                *(uint2*)(st + MT_TILE + off)  = l;
                split4(rb[u], h, l);
                *(uint2*)(st + 2 * MT_TILE + off) = h;
                *(uint2*)(st + 3 * MT_TILE + off) = l;
            }
        }
        __syncthreads();
    }

    const int er0 = m0 + mw * 32 + (lane >> 2);
    const int ec0 = n0 + nw * 64 + (lane & 3) * 2;
    #pragma unroll
    for (int mt = 0; mt < 2; mt++) {
        #pragma unroll
        for (int nt = 0; nt < 8; nt++) {
            const int col = ec0 + nt * 8;
            const float2 bv = *(const float2*)(bias + col);
            #pragma unroll
            for (int half = 0; half < 2; half++) {
                const int row = er0 + mt * 16 + half * 8;
                float vx = cfr[mt][nt][half * 2 + 0] + bv.x;
                float vy = cfr[mt][nt][half * 2 + 1] + bv.y;
                if (RES) {
                    const float2 rv = *(const float2*)(R + (size_t)row * N + col);
                    vx += rv.x; vy += rv.y;
                }
                if (ACT) {
                    vx = 0.5f * vx * (1.0f + erff(vx * 0.70710678118654752f));
                    vy = 0.5f * vy * (1.0f + erff(vy * 0.70710678118654752f));
                }
                *(float2*)(C + (size_t)row * N + col) = make_float2(vx, vy);
            }
        }
    }
}

// ---------------- HMMA flash attention (bf16 hi/lo split) -------------------
// CTA: 128 q-rows x one (b,h). 8 warps, each owns rows wid*16..+15.
// Key tiles of 64; K [key][d] hi/lo, V^T [d][key] hi/lo in smem, pitch 144B.
#define FP_P    144u
#define FQ_H    0u
#define FQ_L    (FQ_H + 128u * FP_P)       // 18432
#define FK_H    (FQ_L + 128u * FP_P)       // 36864
#define FK_L    (FK_H + 64u * FP_P)        // 46080
#define FV_H    (FK_L + 64u * FP_P)        // 55296
#define FV_L    (FV_H + 64u * FP_P)        // 64512
#define FL_SMEM (FV_L + 64u * FP_P)        // 73728

__global__ void __launch_bounds__(256, 1) flash_mma(
    const float* __restrict__ qkv, float* __restrict__ out)
{
    extern __shared__ __align__(16) char sm[];
    const uint32_t sb = smem_u32(sm);

    const int bh = blockIdx.y;
    const int b  = bh / NH, h = bh % NH;
    const int q0 = blockIdx.x * 128;
    const int t  = threadIdx.x, lane = t & 31, wid = t >> 5;

    // ---- load Q tile -> smem hi/lo (128 rows x 16 float4) ----
    #pragma unroll
    for (int u = 0; u < 8; u++) {
        int i = t + u * 256, row = i >> 4, c4 = i & 15;
        float4 v = *(const float4*)(qkv + (size_t)(b * SEQ + q0 + row) * QKV3
                                    + h * HD + c4 * 4);
        uint2 hh, ll;
        split4(v, hh, ll);
        uint32_t off = (uint32_t)row * FP_P + c4 * 8;
        *(uint2*)(sm + FQ_H + off) = hh;
        *(uint2*)(sm + FQ_L + off) = ll;
    }

    // ---- prefetch K/V tile 0 -> regs ----
    float4 rk[4], rv[4];
    {
        #pragma unroll
        for (int u = 0; u < 4; u++) {
            int i = t + u * 256, key = i >> 4, c4 = i & 15;
            const size_t rowb = (size_t)(b * SEQ + key) * QKV3 + h * HD + c4 * 4;
            rk[u] = *(const float4*)(qkv + rowb + DIM);
            rv[u] = *(const float4*)(qkv + rowb + 2 * DIM);
        }
    }
    __syncthreads();

    // ---- Q fragments (resident) ----
    uint32_t qh[4][4], ql[4][4];
    {
        const uint32_t a_lane = (uint32_t)(wid * 16 + (lane & 15)) * FP_P
                              + ((lane >> 4) * 16);
        #pragma unroll
        for (int ks = 0; ks < 4; ks++) {
            ldsm4(qh[ks], sb + FQ_H + a_lane + ks * 32);
            ldsm4(ql[ks], sb + FQ_L + a_lane + ks * 32);
        }
    }

    // ---- store K/V tile 0 -> smem ----
    #pragma unroll
    for (int u = 0; u < 4; u++) {
        int i = t + u * 256, key = i >> 4, c4 = i & 15;
        uint2 hh, ll;
        split4(rk[u], hh, ll);
        uint32_t off = (uint32_t)key * FP_P + c4 * 8;
        *(uint2*)(sm + FK_H + off) = hh;
        *(uint2*)(sm + FK_L + off) = ll;
        const float vv[4] = { rv[u].x, rv[u].y, rv[u].z, rv[u].w };
        #pragma unroll
        for (int j = 0; j < 4; j++) {
            int d = c4 * 4 + j;
            uint32_t bits = __float_as_uint(vv[j]);
            *(uint16_t*)(sm + FV_H + (uint32_t)d * FP_P + key * 2) =
                (uint16_t)(bits >> 16);
            float rem = vv[j] - __uint_as_float(bits & 0xFFFF0000u);
            *(__nv_bfloat16*)(sm + FV_L + (uint32_t)d * FP_P + key * 2) =
                __float2bfloat16(rem);
        }
    }
    __syncthreads();

    // ---- running state ----
    float mr1 = -1e30f, mr2 = -1e30f, lr1 = 0.f, lr2 = 0.f;
    float o[8][4];
    #pragma unroll
    for (int f = 0; f < 8; f++)
        #pragma unroll
        for (int j = 0; j < 4; j++) o[f][j] = 0.f;

    const uint32_t bK = (uint32_t)((lane & 7) + ((lane >> 4) & 1) * 8) * FP_P
                      + ((lane >> 3) & 1) * 16;

    const int NT = SEQ / 64;
    for (int c = 0; c < NT; c++) {
        // prefetch next K/V tile
        if (c + 1 < NT) {
            const int k0 = (c + 1) * 64;
            #pragma unroll
            for (int u = 0; u < 4; u++) {
                int i = t + u * 256, key = i >> 4, c4 = i & 15;
                const size_t rowb = (size_t)(b * SEQ + k0 + key) * QKV3
                                  + h * HD + c4 * 4;
                rk[u] = *(const float4*)(qkv + rowb + DIM);
                rv[u] = *(const float4*)(qkv + rowb + 2 * DIM);
            }
        }

        // ---- S = Q K^T (hi/lo split) ----
        float sf[8][4];
        #pragma unroll
        for (int f = 0; f < 8; f++)
            #pragma unroll
            for (int j = 0; j < 4; j++) sf[f][j] = 0.f;

        #pragma unroll
        for (int p = 0; p < 4; p++) {
            #pragma unroll
            for (int ks = 0; ks < 4; ks++) {
                uint32_t bhf[4], blf[4];
                uint32_t boff = bK + (uint32_t)p * (16 * FP_P) + ks * 32;
                ldsm4(bhf, sb + FK_H + boff);
                ldsm4(blf, sb + FK_L + boff);
                #pragma unroll
                for (int q = 0; q < 2; q++) {
                    float* cc = sf[2 * p + q];
                    mma16816(cc, qh[ks], &bhf[q * 2]);
                    mma16816(cc, qh[ks], &blf[q * 2]);
                    mma16816(cc, ql[ks], &bhf[q * 2]);
                }
            }
        }

        // ---- online softmax (warp-local rows) ----
        float m1 = -1e30f, m2 = -1e30f;
        #pragma unroll
        for (int f = 0; f < 8; f++) {
            sf[f][0] *= 0.125f; sf[f][1] *= 0.125f;
            sf[f][2] *= 0.125f; sf[f][3] *= 0.125f;
            m1 = fmaxf(m1, fmaxf(sf[f][0], sf[f][1]));
            m2 = fmaxf(m2, fmaxf(sf[f][2], sf[f][3]));
        }
        m1 = fmaxf(m1, __shfl_xor_sync(0xffffffffu, m1, 1));
        m1 = fmaxf(m1, __shfl_xor_sync(0xffffffffu, m1, 2));
        m2 = fmaxf(m2, __shfl_xor_sync(0xffffffffu, m2, 1));
        m2 = fmaxf(m2, __shfl_xor_sync(0xffffffffu, m2, 2));

        const float mn1 = fmaxf(mr1, m1), mn2 = fmaxf(mr2, m2);
        const float corr1 = __expf(mr1 - mn1), corr2 = __expf(mr2 - mn2);
        float r1 = 0.f, r2 = 0.f;
        #pragma unroll
        for (int f = 0; f < 8; f++) {
            sf[f][0] = __expf(sf[f][0] - mn1);
            sf[f][1] = __expf(sf[f][1] - mn1);
            sf[f][2] = __expf(sf[f][2] - mn2);
            sf[f][3] = __expf(sf[f][3] - mn2);
            r1 += sf[f][0] + sf[f][1];
            r2 += sf[f][2] + sf[f][3];
        }
        r1 += __shfl_xor_sync(0xffffffffu, r1, 1);
        r1 += __shfl_xor_sync(0xffffffffu, r1, 2);
        r2 += __shfl_xor_sync(0xffffffffu, r2, 1);
        r2 += __shfl_xor_sync(0xffffffffu, r2, 2);
        lr1 = lr1 * corr1 + r1;
        lr2 = lr2 * corr2 + r2;
        mr1 = mn1; mr2 = mn2;
        #pragma unroll
        for (int f = 0; f < 8; f++) {
            o[f][0] *= corr1; o[f][1] *= corr1;
            o[f][2] *= corr2; o[f][3] *= corr2;
        }

        // ---- O += P V (hi/lo split; P repacked in registers) ----
        #pragma unroll
        for (int ks2 = 0; ks2 < 4; ks2++) {
            const int f = 2 * ks2;
            uint32_t ph[4], pl[4];
            ph[0] = hipack(sf[f][0],     sf[f][1]);
            ph[1] = hipack(sf[f][2],     sf[f][3]);
            ph[2] = hipack(sf[f + 1][0], sf[f + 1][1]);
            ph[3] = hipack(sf[f + 1][2], sf[f + 1][3]);
            pl[0] = lopack(sf[f][0],     sf[f][1]);
            pl[1] = lopack(sf[f][2],     sf[f][3]);
            pl[2] = lopack(sf[f + 1][0], sf[f + 1][1]);
            pl[3] = lopack(sf[f + 1][2], sf[f + 1][3]);
            #pragma unroll
            for (int p = 0; p < 4; p++) {
                uint32_t vh[4], vl[4];
                uint32_t boff = bK + (uint32_t)p * (16 * FP_P) + ks2 * 32;
                ldsm4(vh, sb + FV_H + boff);
                ldsm4(vl, sb + FV_L + boff);
                #pragma unroll
                for (int q = 0; q < 2; q++) {
                    float* cc = o[2 * p + q];
                    mma16816(cc, ph, &vh[q * 2]);
                    mma16816(cc, ph, &vl[q * 2]);
                    mma16816(cc, pl, &vh[q * 2]);
                }
            }
        }
        __syncthreads();

        // ---- store prefetched tile ----
        if (c + 1 < NT) {
            #pragma unroll
            for (int u = 0; u < 4; u++) {
                int i = t + u * 256, key = i >> 4, c4 = i & 15;
                uint2 hh, ll;
                split4(rk[u], hh, ll);
                uint32_t off = (uint32_t)key * FP_P + c4 * 8;
                *(uint2*)(sm + FK_H + off) = hh;
                *(uint2*)(sm + FK_L + off) = ll;
                const float vv[4] = { rv[u].x, rv[u].y, rv[u].z, rv[u].w };
                #pragma unroll
                for (int j = 0; j < 4; j++) {
                    int d = c4 * 4 + j;
                    uint32_t bits = __float_as_uint(vv[j]);
                    *(uint16_t*)(sm + FV_H + (uint32_t)d * FP_P + key * 2) =
                        (uint16_t)(bits >> 16);
                    float rem = vv[j] - __uint_as_float(bits & 0xFFFF0000u);
                    *(__nv_bfloat16*)(sm + FV_L + (uint32_t)d * FP_P + key * 2) =
                        __float2bfloat16(rem);
                }
            }
            __syncthreads();
        }
    }

    // ---- write O / l ----
    const float il1 = 1.0f / lr1, il2 = 1.0f / lr2;
    const int row1 = b * SEQ + q0 + wid * 16 + (lane >> 2);
    #pragma unroll
    for (int f = 0; f < 8; f++) {
        const int col = h * HD + f * 8 + (lane & 3) * 2;
        *(float2*)(out + (size_t)row1 * DIM + col) =
            make_float2(o[f][0] * il1, o[f][1] * il1);
        *(float2*)(out + (size_t)(row1 + 8) * DIM + col) =
            make_float2(o[f][2] * il2, o[f][3] * il2);
    }
}

// ---------------------------------------------------------------------------
extern "C" void kernel_launch(void* const* d_in, const int* in_sizes, int n_in,
                              void* d_out, int out_size)
{
    const float* x      = (const float*)d_in[0];
    const float* ln1_w  = (const float*)d_in[1];
    const float* ln1_b  = (const float*)d_in[2];
    const float* qkv_w  = (const float*)d_in[3];
    const float* qkv_b  = (const float*)d_in[4];
    const float* proj_w = (const float*)d_in[5];
    const float* proj_b = (const float*)d_in[6];
    const float* ln2_w  = (const float*)d_in[7];
    const float* ln2_b  = (const float*)d_in[8];
    const float* fc1_w  = (const float*)d_in[9];
    const float* fc1_b  = (const float*)d_in[10];
    const float* fc2_w  = (const float*)d_in[11];
    const float* fc2_b  = (const float*)d_in[12];
    float* out = (float*)d_out;

    float *p_ln, *p_qkv, *p_att, *p_res, *p_h;
    cudaGetSymbolAddress((void**)&p_ln,  g_ln);
    cudaGetSymbolAddress((void**)&p_qkv, g_qkv);
    cudaGetSymbolAddress((void**)&p_att, g_att);
    cudaGetSymbolAddress((void**)&p_res, g_res);
    cudaGetSymbolAddress((void**)&p_h,   g_h);

    cudaFuncSetAttribute(flash_mma,
                         cudaFuncAttributeMaxDynamicSharedMemorySize, FL_SMEM);
    cudaFuncSetAttribute(gemm_mma<0, 0>,
                         cudaFuncAttributeMaxDynamicSharedMemorySize, MT_SMEM);
    cudaFuncSetAttribute(gemm_mma<0, 1>,
                         cudaFuncAttributeMaxDynamicSharedMemorySize, MT_SMEM);
    cudaFuncSetAttribute(gemm_mma<1, 0>,
                         cudaFuncAttributeMaxDynamicSharedMemorySize, MT_SMEM);

    // 1) ln1(x) -> g_ln
    ln_kernel<<<ROWS, 256>>>(x, ln1_w, ln1_b, p_ln);
    // 2) qkv = ln1 @ qkv_w^T + qkv_b -> g_qkv
    gemm_mma<0, 0><<<dim3(QKV3 / 128, ROWS / 128), 256, MT_SMEM>>>(
        p_ln, qkv_w, qkv_b, nullptr, p_qkv, ROWS, QKV3, DIM);
    // 3) attention -> g_att
    flash_mma<<<dim3(SEQ / 128, 4 * NH), 256, FL_SMEM>>>(p_qkv, p_att);
    // 4) x1 = att @ proj_w^T + proj_b + x -> g_res
    gemm_mma<0, 1><<<dim3(DIM / 128, ROWS / 128), 256, MT_SMEM>>>(
        p_att, proj_w, proj_b, x, p_res, ROWS, DIM, DIM);
    // 5) ln2(x1) -> g_ln
    ln_kernel<<<ROWS, 256>>>(p_res, ln2_w, ln2_b, p_ln);
    // 6) h = gelu(ln2 @ fc1_w^T + fc1_b) -> g_h
    gemm_mma<1, 0><<<dim3(HID / 128, ROWS / 128), 256, MT_SMEM>>>(
        p_ln, fc1_w, fc1_b, nullptr, p_h, ROWS, HID, DIM);
    // 7) out = h @ fc2_w^T + fc2_b + x1
    gemm_mma<0, 1><<<dim3(DIM / 128, ROWS / 128), 256, MT_SMEM>>>(
        p_h, fc2_w, fc2_b, p_res, out, ROWS, DIM, HID);
}